// round 2
// baseline (speedup 1.0000x reference)
#include <cuda_runtime.h>
#include <cuda_bf16.h>
#include <math.h>

// Problem constants
#define NN 100000
#define EE 200000
#define BB 2048
#define DD 256
#define LL 5
#define HID 512
#define BN_EPS 1e-5f
#define STATS_BLOCKS 512

// ---------------- scratch (device globals; no allocation allowed) ------------
__device__ float g_h[NN * DD];          // node features
__device__ float g_agg[NN * DD];        // aggregation buffer, reused as z
__device__ float g_t1[(size_t)NN * HID];// hidden activations
__device__ int   g_deg[NN];
__device__ int   g_rowptr[NN + 1];
__device__ int   g_cursor[NN];
__device__ int   g_eid[EE];
__device__ float g_partial[2 * STATS_BLOCKS * DD];
__device__ float g_stats[2 * DD];       // [0:256) mean, [256:512) rstd
__device__ float g_pooled[BB * DD];

// ---------------- CSR build ----------------
__global__ void k_zero_deg() {
    int i = blockIdx.x * blockDim.x + threadIdx.x;
    if (i < NN) g_deg[i] = 0;
}

__global__ void k_hist(const int* __restrict__ edge_index) {
    int e = blockIdx.x * blockDim.x + threadIdx.x;
    if (e < EE) atomicAdd(&g_deg[edge_index[EE + e]], 1);
}

// single-block chunked exclusive scan: deg -> rowptr
__global__ void k_scan() {
    __shared__ int s[1024];
    __shared__ int carry;
    int tid = threadIdx.x;
    if (tid == 0) { carry = 0; g_rowptr[0] = 0; }
    __syncthreads();
    for (int base = 0; base < NN; base += 1024) {
        int i = base + tid;
        int v = (i < NN) ? g_deg[i] : 0;
        s[tid] = v;
        __syncthreads();
        for (int off = 1; off < 1024; off <<= 1) {
            int t = (tid >= off) ? s[tid - off] : 0;
            __syncthreads();
            s[tid] += t;
            __syncthreads();
        }
        if (i < NN) g_rowptr[i + 1] = carry + s[tid];
        __syncthreads();
        if (tid == 0) carry += s[1023];
        __syncthreads();
    }
}

__global__ void k_cursor() {
    int i = blockIdx.x * blockDim.x + threadIdx.x;
    if (i < NN) g_cursor[i] = g_rowptr[i];
}

__global__ void k_scatter(const int* __restrict__ edge_index) {
    int e = blockIdx.x * blockDim.x + threadIdx.x;
    if (e < EE) {
        int pos = atomicAdd(&g_cursor[edge_index[EE + e]], 1);
        g_eid[pos] = e;
    }
}

// deterministic edge ordering (fixed fp reduction order)
__global__ void k_sortseg() {
    int i = blockIdx.x * blockDim.x + threadIdx.x;
    if (i >= NN) return;
    int s = g_rowptr[i], e = g_rowptr[i + 1];
    for (int a = s + 1; a < e; a++) {
        int v = g_eid[a];
        int b = a - 1;
        while (b >= s && g_eid[b] > v) { g_eid[b + 1] = g_eid[b]; b--; }
        g_eid[b + 1] = v;
    }
}

// ---------------- h init ----------------
__global__ void k_init_h(const int* __restrict__ x,
                         const float* __restrict__ emb1,
                         const float* __restrict__ emb2) {
    int i = blockIdx.x;     // node
    int d = threadIdx.x;    // feature
    int a = x[i * 2 + 0], c = x[i * 2 + 1];
    g_h[i * DD + d] = emb1[a * DD + d] + emb2[c * DD + d];
}

// ---------------- aggregation: agg = h + self_e + sum_in (h[src] + e) -------
__global__ void k_agg(const float* __restrict__ e1,   // layer slice: 5 x D
                      const float* __restrict__ e2,   // layer slice: 3 x D
                      const int* __restrict__ edge_index,
                      const int* __restrict__ edge_attr) {
    int i = blockIdx.x;
    int d = threadIdx.x;
    __shared__ float s1[5 * DD];
    __shared__ float s2[3 * DD];
    for (int t = d; t < 5 * DD; t += DD) s1[t] = e1[t];
    for (int t = d; t < 3 * DD; t += DD) s2[t] = e2[t];
    __syncthreads();
    float acc = g_h[i * DD + d] + s1[4 * DD + d] + s2[d];
    int s = g_rowptr[i], e = g_rowptr[i + 1];
    for (int p = s; p < e; p++) {
        int eid = g_eid[p];
        int sn = edge_index[eid];             // src row
        int bt = edge_attr[eid * 2 + 0];
        int bd = edge_attr[eid * 2 + 1];
        acc += g_h[sn * DD + d] + s1[bt * DD + d] + s2[bd * DD + d];
    }
    g_agg[i * DD + d] = acc;
}

// ---------------- fp32 SGEMM: C = A @ B + bias (opt relu) -------------------
// A/C are device-global scratch buffers selected by template flag: referencing
// the __device__ symbols in DEVICE code (host code must not take their address).
#define BM 128
#define BN 128
#define BKK 8
#define TM 8
#define TN 8

template<int ASRC /*0: g_agg, 1: g_t1*/, int CDST /*0: g_t1, 1: g_agg*/>
__global__ __launch_bounds__(256)
void sgemm_bias(const float* __restrict__ Bm,
                const float* __restrict__ bias,
                int M, int Nc, int K, int relu) {
    const float* __restrict__ A = (ASRC == 0) ? (const float*)g_agg : (const float*)g_t1;
    float* __restrict__ C = (CDST == 0) ? (float*)g_t1 : (float*)g_agg;

    __shared__ float As[BKK][BM];
    __shared__ float Bs[BKK][BN];
    int tid = threadIdx.x;
    int tx = tid % 16, ty = tid / 16;
    int m0 = blockIdx.y * BM, n0 = blockIdx.x * BN;
    float acc[TM][TN];
#pragma unroll
    for (int i = 0; i < TM; i++)
#pragma unroll
        for (int j = 0; j < TN; j++) acc[i][j] = 0.f;

    int arow = tid >> 1;          // 0..127
    int acol = (tid & 1) * 4;     // 0 / 4
    int brow = tid >> 5;          // 0..7
    int bcol = (tid & 31) * 4;    // 0..124

    for (int k0 = 0; k0 < K; k0 += BKK) {
        float4 av = make_float4(0.f, 0.f, 0.f, 0.f);
        if (m0 + arow < M)
            av = *reinterpret_cast<const float4*>(A + (size_t)(m0 + arow) * K + k0 + acol);
        As[acol + 0][arow] = av.x;
        As[acol + 1][arow] = av.y;
        As[acol + 2][arow] = av.z;
        As[acol + 3][arow] = av.w;
        float4 bv = *reinterpret_cast<const float4*>(Bm + (size_t)(k0 + brow) * Nc + n0 + bcol);
        *reinterpret_cast<float4*>(&Bs[brow][bcol]) = bv;
        __syncthreads();
#pragma unroll
        for (int k = 0; k < BKK; k++) {
            float ra[TM], rb[TN];
#pragma unroll
            for (int i = 0; i < TM; i++) ra[i] = As[k][ty * TM + i];
#pragma unroll
            for (int j = 0; j < TN; j++) rb[j] = Bs[k][tx * TN + j];
#pragma unroll
            for (int i = 0; i < TM; i++)
#pragma unroll
                for (int j = 0; j < TN; j++) acc[i][j] += ra[i] * rb[j];
        }
        __syncthreads();
    }
#pragma unroll
    for (int i = 0; i < TM; i++) {
        int m = m0 + ty * TM + i;
        if (m >= M) break;
#pragma unroll
        for (int j = 0; j < TN; j += 4) {
            int n = n0 + tx * TN + j;
            float4 v;
            v.x = acc[i][j + 0] + bias[n + 0];
            v.y = acc[i][j + 1] + bias[n + 1];
            v.z = acc[i][j + 2] + bias[n + 2];
            v.w = acc[i][j + 3] + bias[n + 3];
            if (relu) {
                v.x = fmaxf(v.x, 0.f); v.y = fmaxf(v.y, 0.f);
                v.z = fmaxf(v.z, 0.f); v.w = fmaxf(v.w, 0.f);
            }
            *reinterpret_cast<float4*>(C + (size_t)m * Nc + n) = v;
        }
    }
}

// ---------------- batchnorm (deterministic two-stage column stats) ----------
__global__ void k_colstats() {   // z = g_agg (N x D)
    int d = threadIdx.x;
    float s = 0.f, q = 0.f;
    for (int r = blockIdx.x; r < NN; r += gridDim.x) {
        float v = g_agg[(size_t)r * DD + d];
        s += v; q += v * v;
    }
    g_partial[blockIdx.x * DD + d] = s;
    g_partial[(STATS_BLOCKS + blockIdx.x) * DD + d] = q;
}

__global__ void k_colreduce() {
    int d = threadIdx.x;
    float s = 0.f, q = 0.f;
    for (int b = 0; b < STATS_BLOCKS; b++) {
        s += g_partial[b * DD + d];
        q += g_partial[(STATS_BLOCKS + b) * DD + d];
    }
    float mu = s / (float)NN;
    float var = q / (float)NN - mu * mu;
    g_stats[d] = mu;
    g_stats[DD + d] = rsqrtf(var + BN_EPS);
}

__global__ void k_bnrelu(const float* __restrict__ g, const float* __restrict__ b) {
    int idx = blockIdx.x * blockDim.x + threadIdx.x;
    if (idx >= NN * DD) return;
    int d = idx & (DD - 1);
    float z = g_agg[idx];
    float v = (z - g_stats[d]) * g_stats[DD + d] * g[d] + b[d];
    g_h[idx] = fmaxf(v, 0.f);
}

// ---------------- pooling (batch array is sorted -> binary search) ----------
__device__ __forceinline__ int lower_bound_dev(const int* a, int n, int key) {
    int lo = 0, hi = n;
    while (lo < hi) {
        int mid = (lo + hi) >> 1;
        if (a[mid] < key) lo = mid + 1; else hi = mid;
    }
    return lo;
}

__global__ void k_pool(const int* __restrict__ batch) {
    int b = blockIdx.x;
    int d = threadIdx.x;
    __shared__ int lo_s, hi_s;
    if (d == 0) {
        lo_s = lower_bound_dev(batch, NN, b);
        hi_s = lower_bound_dev(batch, NN, b + 1);
    }
    __syncthreads();
    int lo = lo_s, hi = hi_s;
    float s = 0.f;
    for (int i = lo; i < hi; i++) s += g_h[(size_t)i * DD + d];
    float c = (float)(hi - lo);
    g_pooled[b * DD + d] = s / fmaxf(c, 1.f);
}

// ---------------- output MLP ----------------
__global__ void k_out(const float* __restrict__ Wo1, const float* __restrict__ bo1,
                      const float* __restrict__ Wo2, const float* __restrict__ bo2,
                      float* __restrict__ out) {
    int b = blockIdx.x;
    int j = threadIdx.x;  // 128 threads, one hidden unit each
    __shared__ float p[DD];
    __shared__ float r0[128], r1[128];
    p[j] = g_pooled[b * DD + j];
    p[j + 128] = g_pooled[b * DD + 128 + j];
    __syncthreads();
    float acc = bo1[j];
    for (int k = 0; k < DD; k++) acc += p[k] * Wo1[k * 128 + j];
    float hv = (acc > 20.f) ? acc : log1pf(expf(acc));
    r0[j] = hv * Wo2[j * 2 + 0];
    r1[j] = hv * Wo2[j * 2 + 1];
    __syncthreads();
    for (int s = 64; s > 0; s >>= 1) {
        if (j < s) { r0[j] += r0[j + s]; r1[j] += r1[j + s]; }
        __syncthreads();
    }
    if (j == 0) {
        out[b * 2 + 0] = r0[0] + bo2[0];
        out[b * 2 + 1] = r1[0] + bo2[1];
    }
}

// ---------------- launch ----------------
extern "C" void kernel_launch(void* const* d_in, const int* in_sizes, int n_in,
                              void* d_out, int out_size) {
    const int*   x          = (const int*)d_in[0];
    const int*   edge_index = (const int*)d_in[1];
    const int*   edge_attr  = (const int*)d_in[2];
    const int*   batch      = (const int*)d_in[3];
    const float* x_emb1     = (const float*)d_in[4];
    const float* x_emb2     = (const float*)d_in[5];
    const float* edge_emb1  = (const float*)d_in[6];   // L x 5 x D
    const float* edge_emb2  = (const float*)d_in[7];   // L x 3 x D
    const float* W1         = (const float*)d_in[8];   // L x D x 2D
    const float* b1         = (const float*)d_in[9];   // L x 2D
    const float* W2         = (const float*)d_in[10];  // L x 2D x D
    const float* b2         = (const float*)d_in[11];  // L x D
    const float* bn_g       = (const float*)d_in[12];  // L x D
    const float* bn_b       = (const float*)d_in[13];  // L x D
    const float* Wo1        = (const float*)d_in[14];  // D x D/2
    const float* bo1        = (const float*)d_in[15];
    const float* Wo2        = (const float*)d_in[16];  // D/2 x 2
    const float* bo2        = (const float*)d_in[17];
    float* out = (float*)d_out;

    // CSR build (deterministic via per-node sorted edge lists)
    k_zero_deg<<<(NN + 255) / 256, 256>>>();
    k_hist<<<(EE + 255) / 256, 256>>>(edge_index);
    k_scan<<<1, 1024>>>();
    k_cursor<<<(NN + 255) / 256, 256>>>();
    k_scatter<<<(EE + 255) / 256, 256>>>(edge_index);
    k_sortseg<<<(NN + 255) / 256, 256>>>();

    // h init
    k_init_h<<<NN, DD>>>(x, x_emb1, x_emb2);

    for (int l = 0; l < LL; l++) {
        k_agg<<<NN, DD>>>(edge_emb1 + (size_t)l * 5 * DD,
                          edge_emb2 + (size_t)l * 3 * DD,
                          edge_index, edge_attr);
        // GEMM1: g_t1 = relu(g_agg @ W1 + b1)   (N x 512)
        {
            dim3 grid(HID / BN, (NN + BM - 1) / BM);
            sgemm_bias<0, 0><<<grid, 256>>>(W1 + (size_t)l * DD * HID,
                                            b1 + (size_t)l * HID,
                                            NN, HID, DD, 1);
        }
        // GEMM2: g_agg = g_t1 @ W2 + b2   (N x 256)
        {
            dim3 grid(DD / BN, (NN + BM - 1) / BM);
            sgemm_bias<1, 1><<<grid, 256>>>(W2 + (size_t)l * HID * DD,
                                            b2 + (size_t)l * DD,
                                            NN, DD, HID, 0);
        }
        k_colstats<<<STATS_BLOCKS, DD>>>();
        k_colreduce<<<1, DD>>>();
        k_bnrelu<<<(NN * DD + 255) / 256, 256>>>(bn_g + l * DD, bn_b + l * DD);
    }

    k_pool<<<BB, DD>>>(batch);
    k_out<<<BB, 128>>>(Wo1, bo1, Wo2, bo2, out);
}

// round 5
// speedup vs baseline: 1.0621x; 1.0621x over previous
#include <cuda_runtime.h>
#include <cuda_bf16.h>
#include <mma.h>
#include <math.h>
#include <stdint.h>

using namespace nvcuda;

// Problem constants
#define NN 100000
#define NNP 100096          // padded to multiple of 128 for unguarded tile stores
#define EE 200000
#define BB 2048
#define DD 256
#define LL 5
#define HID 512
#define BN_EPS 1e-5f
#define STATS_BLOCKS 512

// ---------------- scratch (device globals; no allocation allowed) ------------
__device__ float g_h[NNP * DD];
__device__ float g_agg[NNP * DD];
__device__ float g_t1[(size_t)NNP * HID];
__device__ float g_w1t[(size_t)LL * HID * DD];   // [l][n][k] = W1[l][k][n], tf32-rounded
__device__ float g_w2t[(size_t)LL * DD * HID];   // [l][n][k] = W2[l][k][n], tf32-rounded
__device__ int   g_deg[NN];
__device__ int   g_rowptr[NN + 1];
__device__ int   g_cursor[NN];
__device__ int   g_eid[EE];
__device__ float g_partial[2 * STATS_BLOCKS * DD];
__device__ float g_stats[2 * DD];
__device__ float g_pooled[BB * DD];

static __device__ __forceinline__ uint32_t f2tf32(float x) {
    uint32_t r; asm("cvt.rna.tf32.f32 %0, %1;" : "=r"(r) : "f"(x)); return r;
}

// ---------------- CSR build ----------------
__global__ void k_zero_deg() {
    int i = blockIdx.x * blockDim.x + threadIdx.x;
    if (i < NN) g_deg[i] = 0;
}

__global__ void k_hist(const int* __restrict__ edge_index) {
    int e = blockIdx.x * blockDim.x + threadIdx.x;
    if (e < EE) atomicAdd(&g_deg[edge_index[EE + e]], 1);
}

__global__ void k_scan() {
    __shared__ int s[1024];
    __shared__ int carry;
    int tid = threadIdx.x;
    if (tid == 0) { carry = 0; g_rowptr[0] = 0; }
    __syncthreads();
    for (int base = 0; base < NN; base += 1024) {
        int i = base + tid;
        int v = (i < NN) ? g_deg[i] : 0;
        s[tid] = v;
        __syncthreads();
        for (int off = 1; off < 1024; off <<= 1) {
            int t = (tid >= off) ? s[tid - off] : 0;
            __syncthreads();
            s[tid] += t;
            __syncthreads();
        }
        if (i < NN) g_rowptr[i + 1] = carry + s[tid];
        __syncthreads();
        if (tid == 0) carry += s[1023];
        __syncthreads();
    }
}

__global__ void k_cursor() {
    int i = blockIdx.x * blockDim.x + threadIdx.x;
    if (i < NN) g_cursor[i] = g_rowptr[i];
}

__global__ void k_scatter(const int* __restrict__ edge_index) {
    int e = blockIdx.x * blockDim.x + threadIdx.x;
    if (e < EE) {
        int pos = atomicAdd(&g_cursor[edge_index[EE + e]], 1);
        g_eid[pos] = e;
    }
}

__global__ void k_sortseg() {
    int i = blockIdx.x * blockDim.x + threadIdx.x;
    if (i >= NN) return;
    int s = g_rowptr[i], e = g_rowptr[i + 1];
    for (int a = s + 1; a < e; a++) {
        int v = g_eid[a];
        int b = a - 1;
        while (b >= s && g_eid[b] > v) { g_eid[b + 1] = g_eid[b]; b--; }
        g_eid[b + 1] = v;
    }
}

// ---------------- weight transpose + tf32 pre-round ----------------
__global__ void k_prep_w1t(const float* __restrict__ W1) {
    int idx = blockIdx.x * blockDim.x + threadIdx.x;
    if (idx >= LL * HID * DD) return;
    int l = idx / (HID * DD);
    int rem = idx - l * (HID * DD);
    int n = rem / DD;
    int k = rem - n * DD;
    g_w1t[idx] = __uint_as_float(f2tf32(W1[(size_t)l * DD * HID + (size_t)k * HID + n]));
}

__global__ void k_prep_w2t(const float* __restrict__ W2) {
    int idx = blockIdx.x * blockDim.x + threadIdx.x;
    if (idx >= LL * DD * HID) return;
    int l = idx / (DD * HID);
    int rem = idx - l * (DD * HID);
    int n = rem / HID;
    int k = rem - n * HID;
    g_w2t[idx] = __uint_as_float(f2tf32(W2[(size_t)l * HID * DD + (size_t)k * DD + n]));
}

// ---------------- h init ----------------
__global__ void k_init_h(const int* __restrict__ x,
                         const float* __restrict__ emb1,
                         const float* __restrict__ emb2) {
    int i = blockIdx.x;
    int d = threadIdx.x;
    int a = x[i * 2 + 0], c = x[i * 2 + 1];
    g_h[i * DD + d] = emb1[a * DD + d] + emb2[c * DD + d];
}

// ---------------- aggregation ----------------
__global__ void k_agg(const float* __restrict__ e1,
                      const float* __restrict__ e2,
                      const int* __restrict__ edge_index,
                      const int* __restrict__ edge_attr) {
    int i = blockIdx.x;
    int d = threadIdx.x;
    __shared__ float s1[5 * DD];
    __shared__ float s2[3 * DD];
    for (int t = d; t < 5 * DD; t += DD) s1[t] = e1[t];
    for (int t = d; t < 3 * DD; t += DD) s2[t] = e2[t];
    __syncthreads();
    float acc = g_h[i * DD + d] + s1[4 * DD + d] + s2[d];
    int s = g_rowptr[i], e = g_rowptr[i + 1];
    for (int p = s; p < e; p++) {
        int eid = g_eid[p];
        int sn = edge_index[eid];
        int bt = edge_attr[eid * 2 + 0];
        int bd = edge_attr[eid * 2 + 1];
        acc += g_h[sn * DD + d] + s1[bt * DD + d] + s2[bd * DD + d];
    }
    g_agg[i * DD + d] = acc;
}

// =================== wmma tf32 GEMM ===================
// G==0: g_t1 = g_agg @ W1              (raw, no bias/relu — fused into G==1 staging)
// G==1: g_agg = relu(g_t1 + b1) @ W2   (raw; b2 dropped — BN-invariant)
// BM=128, BN=64, BK=64. 8 warps in 4(row) x 2(col); warp tile 32x32 = 2x2 wmma tiles.
#define GLD 68                      // SMEM leading dim (pad 4)
#define GEMM_SMEM ((128 * GLD + 64 * GLD) * 4)

template<int G>
__global__ __launch_bounds__(256)
void gemm_wmma(const float* __restrict__ bias, int l) {
    constexpr int K  = (G == 0) ? DD : HID;
    constexpr int NC = (G == 0) ? HID : DD;

    const float* __restrict__ A = (G == 0) ? (const float*)g_agg : (const float*)g_t1;
    float* __restrict__ C = (G == 0) ? (float*)g_t1 : (float*)g_agg;
    const float* __restrict__ BT =
        ((G == 0) ? (const float*)g_w1t : (const float*)g_w2t) + (size_t)l * K * NC;

    extern __shared__ float sm[];
    float* As = sm;               // [128][GLD]
    float* Bs = sm + 128 * GLD;   // [64][GLD]

    const int tid = threadIdx.x;
    const int wid = tid >> 5;
    const int warpRow = wid >> 1;   // 0..3
    const int warpCol = wid & 1;    // 0..1
    const int m0 = blockIdx.y * 128;
    const int n0 = blockIdx.x * 64;

    // staging coords
    const int arow = tid >> 1;             // 0..127
    const int acb  = (tid & 1) * 32;       // col base 0/32
    const bool avalid = (m0 + arow) < NN;
    const int brow = tid & 63;             // 0..63 (n)
    const int bcb  = (tid >> 6) * 16;      // col base 0/16/32/48

    wmma::fragment<wmma::accumulator, 16, 16, 8, float> acc[2][2];
#pragma unroll
    for (int t = 0; t < 2; t++)
#pragma unroll
        for (int u = 0; u < 2; u++) wmma::fill_fragment(acc[t][u], 0.0f);

    for (int k0 = 0; k0 < K; k0 += 64) {
        // stage A (with optional fused bias+relu), tf32-rounded
        {
            const float* src = A + (size_t)(m0 + arow) * K + k0 + acb;
            float* dst = As + arow * GLD + acb;
#pragma unroll
            for (int i = 0; i < 8; i++) {
                float4 v = avalid ? *(const float4*)(src + i * 4)
                                  : make_float4(0.f, 0.f, 0.f, 0.f);
                if (G == 1 && avalid) {
                    const float* bp = bias + k0 + acb + i * 4;
                    v.x = fmaxf(v.x + bp[0], 0.f);
                    v.y = fmaxf(v.y + bp[1], 0.f);
                    v.z = fmaxf(v.z + bp[2], 0.f);
                    v.w = fmaxf(v.w + bp[3], 0.f);
                }
                float4 o;
                o.x = __uint_as_float(f2tf32(v.x));
                o.y = __uint_as_float(f2tf32(v.y));
                o.z = __uint_as_float(f2tf32(v.z));
                o.w = __uint_as_float(f2tf32(v.w));
                *(float4*)(dst + i * 4) = o;
            }
        }
        // stage B (already tf32-rounded)
        {
            const float* src = BT + (size_t)(n0 + brow) * K + k0 + bcb;
            float* dst = Bs + brow * GLD + bcb;
#pragma unroll
            for (int i = 0; i < 4; i++)
                *(float4*)(dst + i * 4) = *(const float4*)(src + i * 4);
        }
        __syncthreads();

#pragma unroll
        for (int ks = 0; ks < 8; ks++) {
            wmma::fragment<wmma::matrix_a, 16, 16, 8, wmma::precision::tf32, wmma::row_major> af[2];
            wmma::fragment<wmma::matrix_b, 16, 16, 8, wmma::precision::tf32, wmma::col_major> bf[2];
#pragma unroll
            for (int t = 0; t < 2; t++)
                wmma::load_matrix_sync(af[t], As + (warpRow * 32 + t * 16) * GLD + ks * 8, GLD);
#pragma unroll
            for (int u = 0; u < 2; u++)
                wmma::load_matrix_sync(bf[u], Bs + (warpCol * 32 + u * 16) * GLD + ks * 8, GLD);
#pragma unroll
            for (int t = 0; t < 2; t++)
#pragma unroll
                for (int u = 0; u < 2; u++)
                    wmma::mma_sync(acc[t][u], af[t], bf[u], acc[t][u]);
        }
        __syncthreads();
    }

    // epilogue: raw store (buffers padded to NNP rows)
#pragma unroll
    for (int t = 0; t < 2; t++)
#pragma unroll
        for (int u = 0; u < 2; u++) {
            int m = m0 + warpRow * 32 + t * 16;
            int n = n0 + warpCol * 32 + u * 16;
            wmma::store_matrix_sync(C + (size_t)m * NC + n, acc[t][u], NC, wmma::mem_row_major);
        }
}

// ---------------- batchnorm ----------------
__global__ void k_colstats() {
    int d = threadIdx.x;
    float s = 0.f, q = 0.f;
    for (int r = blockIdx.x; r < NN; r += gridDim.x) {
        float v = g_agg[(size_t)r * DD + d];
        s += v; q += v * v;
    }
    g_partial[blockIdx.x * DD + d] = s;
    g_partial[(STATS_BLOCKS + blockIdx.x) * DD + d] = q;
}

__global__ void k_colreduce() {
    int d = threadIdx.x;
    float s = 0.f, q = 0.f;
    for (int b = 0; b < STATS_BLOCKS; b++) {
        s += g_partial[b * DD + d];
        q += g_partial[(STATS_BLOCKS + b) * DD + d];
    }
    float mu = s / (float)NN;
    float var = q / (float)NN - mu * mu;
    g_stats[d] = mu;
    g_stats[DD + d] = rsqrtf(var + BN_EPS);
}

__global__ void k_bnrelu(const float* __restrict__ g, const float* __restrict__ b) {
    int idx = blockIdx.x * blockDim.x + threadIdx.x;
    if (idx >= NN * DD) return;
    int d = idx & (DD - 1);
    float z = g_agg[idx];
    float v = (z - g_stats[d]) * g_stats[DD + d] * g[d] + b[d];
    g_h[idx] = fmaxf(v, 0.f);
}

// ---------------- pooling ----------------
__device__ __forceinline__ int lower_bound_dev(const int* a, int n, int key) {
    int lo = 0, hi = n;
    while (lo < hi) {
        int mid = (lo + hi) >> 1;
        if (a[mid] < key) lo = mid + 1; else hi = mid;
    }
    return lo;
}

__global__ void k_pool(const int* __restrict__ batch) {
    int b = blockIdx.x;
    int d = threadIdx.x;
    __shared__ int lo_s, hi_s;
    if (d == 0) {
        lo_s = lower_bound_dev(batch, NN, b);
        hi_s = lower_bound_dev(batch, NN, b + 1);
    }
    __syncthreads();
    int lo = lo_s, hi = hi_s;
    float s = 0.f;
    for (int i = lo; i < hi; i++) s += g_h[(size_t)i * DD + d];
    float c = (float)(hi - lo);
    g_pooled[b * DD + d] = s / fmaxf(c, 1.f);
}

// ---------------- output MLP ----------------
__global__ void k_out(const float* __restrict__ Wo1, const float* __restrict__ bo1,
                      const float* __restrict__ Wo2, const float* __restrict__ bo2,
                      float* __restrict__ out) {
    int b = blockIdx.x;
    int j = threadIdx.x;
    __shared__ float p[DD];
    __shared__ float r0[128], r1[128];
    p[j] = g_pooled[b * DD + j];
    p[j + 128] = g_pooled[b * DD + 128 + j];
    __syncthreads();
    float acc = bo1[j];
    for (int k = 0; k < DD; k++) acc += p[k] * Wo1[k * 128 + j];
    float hv = (acc > 20.f) ? acc : log1pf(expf(acc));
    r0[j] = hv * Wo2[j * 2 + 0];
    r1[j] = hv * Wo2[j * 2 + 1];
    __syncthreads();
    for (int s = 64; s > 0; s >>= 1) {
        if (j < s) { r0[j] += r0[j + s]; r1[j] += r1[j + s]; }
        __syncthreads();
    }
    if (j == 0) {
        out[b * 2 + 0] = r0[0] + bo2[0];
        out[b * 2 + 1] = r1[0] + bo2[1];
    }
}

// ---------------- launch ----------------
extern "C" void kernel_launch(void* const* d_in, const int* in_sizes, int n_in,
                              void* d_out, int out_size) {
    const int*   x          = (const int*)d_in[0];
    const int*   edge_index = (const int*)d_in[1];
    const int*   edge_attr  = (const int*)d_in[2];
    const int*   batch      = (const int*)d_in[3];
    const float* x_emb1     = (const float*)d_in[4];
    const float* x_emb2     = (const float*)d_in[5];
    const float* edge_emb1  = (const float*)d_in[6];
    const float* edge_emb2  = (const float*)d_in[7];
    const float* W1         = (const float*)d_in[8];
    const float* b1         = (const float*)d_in[9];
    const float* W2         = (const float*)d_in[10];
    const float* b2         = (const float*)d_in[11];  // dropped (BN-invariant)
    const float* bn_g       = (const float*)d_in[12];
    const float* bn_b       = (const float*)d_in[13];
    const float* Wo1        = (const float*)d_in[14];
    const float* bo1        = (const float*)d_in[15];
    const float* Wo2        = (const float*)d_in[16];
    const float* bo2        = (const float*)d_in[17];
    float* out = (float*)d_out;
    (void)b2;

    cudaFuncSetAttribute(gemm_wmma<0>, cudaFuncAttributeMaxDynamicSharedMemorySize, GEMM_SMEM);
    cudaFuncSetAttribute(gemm_wmma<1>, cudaFuncAttributeMaxDynamicSharedMemorySize, GEMM_SMEM);

    // CSR build
    k_zero_deg<<<(NN + 255) / 256, 256>>>();
    k_hist<<<(EE + 255) / 256, 256>>>(edge_index);
    k_scan<<<1, 1024>>>();
    k_cursor<<<(NN + 255) / 256, 256>>>();
    k_scatter<<<(EE + 255) / 256, 256>>>(edge_index);
    k_sortseg<<<(NN + 255) / 256, 256>>>();

    // weight transpose + tf32 pre-round
    k_prep_w1t<<<(LL * HID * DD + 255) / 256, 256>>>(W1);
    k_prep_w2t<<<(LL * DD * HID + 255) / 256, 256>>>(W2);

    k_init_h<<<NN, DD>>>(x, x_emb1, x_emb2);

    const int MT = (NNP + 127) / 128;  // 782
    for (int l = 0; l < LL; l++) {
        k_agg<<<NN, DD>>>(edge_emb1 + (size_t)l * 5 * DD,
                          edge_emb2 + (size_t)l * 3 * DD,
                          edge_index, edge_attr);
        {   // GEMM1: t1 = agg @ W1 (raw)
            dim3 grid(HID / 64, MT);
            gemm_wmma<0><<<grid, 256, GEMM_SMEM>>>(b1 + (size_t)l * HID, l);
        }
        {   // GEMM2: agg = relu(t1 + b1) @ W2 (raw; b2 dropped)
            dim3 grid(DD / 64, MT);
            gemm_wmma<1><<<grid, 256, GEMM_SMEM>>>(b1 + (size_t)l * HID, l);
        }
        k_colstats<<<STATS_BLOCKS, DD>>>();
        k_colreduce<<<1, DD>>>();
        k_bnrelu<<<(NN * DD + 255) / 256, 256>>>(bn_g + l * DD, bn_b + l * DD);
    }

    k_pool<<<BB, DD>>>(batch);
    k_out<<<BB, 128>>>(Wo1, bo1, Wo2, bo2, out);
}

// round 6
// speedup vs baseline: 1.3206x; 1.2434x over previous
#include <cuda_runtime.h>
#include <cuda_bf16.h>
#include <mma.h>
#include <math.h>
#include <stdint.h>

using namespace nvcuda;

// Problem constants
#define NN 100000
#define NNP 100096          // padded to multiple of 128 for unguarded tile stores
#define EE 200000
#define BB 2048
#define DD 256
#define LL 5
#define HID 512
#define BN_EPS 1e-5f
#define STATS_BLOCKS 512

// ---------------- scratch (device globals; no allocation allowed) ------------
__device__ float g_h[NNP * DD];
__device__ float g_agg[NNP * DD];
__device__ float g_t1[(size_t)NNP * HID];
__device__ float g_w1t[(size_t)LL * HID * DD];   // [l][n][k] = W1[l][k][n], tf32-rounded
__device__ float g_w2t[(size_t)LL * DD * HID];   // [l][n][k] = W2[l][k][n], tf32-rounded
__device__ int   g_deg[NN];
__device__ int   g_rowptr[NN + 1];
__device__ int   g_cursor[NN];
__device__ int   g_eid[EE];
__device__ float g_partial[2 * STATS_BLOCKS * DD];
__device__ float g_stats[2 * DD];
__device__ float g_pooled[BB * DD];

static __device__ __forceinline__ uint32_t f2tf32(float x) {
    uint32_t r; asm("cvt.rna.tf32.f32 %0, %1;" : "=r"(r) : "f"(x)); return r;
}

// ---------------- CSR build ----------------
__global__ void k_zero_deg() {
    int i = blockIdx.x * blockDim.x + threadIdx.x;
    if (i < NN) g_deg[i] = 0;
}

__global__ void k_hist(const int* __restrict__ edge_index) {
    int e = blockIdx.x * blockDim.x + threadIdx.x;
    if (e < EE) atomicAdd(&g_deg[edge_index[EE + e]], 1);
}

__global__ void k_scan() {
    __shared__ int s[1024];
    __shared__ int carry;
    int tid = threadIdx.x;
    if (tid == 0) { carry = 0; g_rowptr[0] = 0; }
    __syncthreads();
    for (int base = 0; base < NN; base += 1024) {
        int i = base + tid;
        int v = (i < NN) ? g_deg[i] : 0;
        s[tid] = v;
        __syncthreads();
        for (int off = 1; off < 1024; off <<= 1) {
            int t = (tid >= off) ? s[tid - off] : 0;
            __syncthreads();
            s[tid] += t;
            __syncthreads();
        }
        if (i < NN) g_rowptr[i + 1] = carry + s[tid];
        __syncthreads();
        if (tid == 0) carry += s[1023];
        __syncthreads();
    }
}

__global__ void k_cursor() {
    int i = blockIdx.x * blockDim.x + threadIdx.x;
    if (i < NN) g_cursor[i] = g_rowptr[i];
}

__global__ void k_scatter(const int* __restrict__ edge_index) {
    int e = blockIdx.x * blockDim.x + threadIdx.x;
    if (e < EE) {
        int pos = atomicAdd(&g_cursor[edge_index[EE + e]], 1);
        g_eid[pos] = e;
    }
}

__global__ void k_sortseg() {
    int i = blockIdx.x * blockDim.x + threadIdx.x;
    if (i >= NN) return;
    int s = g_rowptr[i], e = g_rowptr[i + 1];
    for (int a = s + 1; a < e; a++) {
        int v = g_eid[a];
        int b = a - 1;
        while (b >= s && g_eid[b] > v) { g_eid[b + 1] = g_eid[b]; b--; }
        g_eid[b + 1] = v;
    }
}

// ---------------- weight transpose + tf32 pre-round ----------------
__global__ void k_prep_w1t(const float* __restrict__ W1) {
    int idx = blockIdx.x * blockDim.x + threadIdx.x;
    if (idx >= LL * HID * DD) return;
    int l = idx / (HID * DD);
    int rem = idx - l * (HID * DD);
    int n = rem / DD;
    int k = rem - n * DD;
    g_w1t[idx] = __uint_as_float(f2tf32(W1[(size_t)l * DD * HID + (size_t)k * HID + n]));
}

__global__ void k_prep_w2t(const float* __restrict__ W2) {
    int idx = blockIdx.x * blockDim.x + threadIdx.x;
    if (idx >= LL * DD * HID) return;
    int l = idx / (DD * HID);
    int rem = idx - l * (DD * HID);
    int n = rem / HID;
    int k = rem - n * HID;
    g_w2t[idx] = __uint_as_float(f2tf32(W2[(size_t)l * HID * DD + (size_t)k * DD + n]));
}

// ---------------- h init ----------------
__global__ void k_init_h(const int* __restrict__ x,
                         const float* __restrict__ emb1,
                         const float* __restrict__ emb2) {
    int i = blockIdx.x;
    int d = threadIdx.x;
    int a = x[i * 2 + 0], c = x[i * 2 + 1];
    g_h[i * DD + d] = emb1[a * DD + d] + emb2[c * DD + d];
}

// ---------------- aggregation ----------------
__global__ void k_agg(const float* __restrict__ e1,
                      const float* __restrict__ e2,
                      const int* __restrict__ edge_index,
                      const int* __restrict__ edge_attr) {
    int i = blockIdx.x;
    int d = threadIdx.x;
    __shared__ float s1[5 * DD];
    __shared__ float s2[3 * DD];
    for (int t = d; t < 5 * DD; t += DD) s1[t] = e1[t];
    for (int t = d; t < 3 * DD; t += DD) s2[t] = e2[t];
    __syncthreads();
    float acc = g_h[i * DD + d] + s1[4 * DD + d] + s2[d];
    int s = g_rowptr[i], e = g_rowptr[i + 1];
    for (int p = s; p < e; p++) {
        int eid = g_eid[p];
        int sn = edge_index[eid];
        int bt = edge_attr[eid * 2 + 0];
        int bd = edge_attr[eid * 2 + 1];
        acc += g_h[sn * DD + d] + s1[bt * DD + d] + s2[bd * DD + d];
    }
    g_agg[i * DD + d] = acc;
}

// =================== wmma tf32 GEMM (double-buffered) ===================
// G==0: g_t1 = g_agg @ W1              (raw; bias/relu fused into G==1 staging)
// G==1: g_agg = relu(g_t1 + b1) @ W2   (raw; b2 dropped — BN-invariant)
// BM=128, BN=128, BK=32. 8 warps = 2(M) x 4(N); warp tile 64x32 = 4x2 wmma tiles.
#define GLD 36                            // SMEM leading dim (32 + pad 4)
#define BUF_FLOATS (2 * 128 * GLD)        // A + B per buffer
#define GEMM_SMEM (2 * BUF_FLOATS * 4)    // 73728 bytes

template<int G>
__global__ __launch_bounds__(256)
void gemm_wmma(const float* __restrict__ bias, int l) {
    constexpr int K  = (G == 0) ? DD : HID;
    constexpr int NC = (G == 0) ? HID : DD;
    constexpr int NIT = K / 32;

    const float* __restrict__ A = (G == 0) ? (const float*)g_agg : (const float*)g_t1;
    float* __restrict__ C = (G == 0) ? (float*)g_t1 : (float*)g_agg;
    const float* __restrict__ BT =
        ((G == 0) ? (const float*)g_w1t : (const float*)g_w2t) + (size_t)l * K * NC;

    extern __shared__ float sm[];

    const int tid = threadIdx.x;
    const int wid = tid >> 5;
    const int warpM = wid & 1;    // 0..1  (64 rows each)
    const int warpN = wid >> 1;   // 0..3  (32 cols each)
    const int m0 = blockIdx.y * 128;
    const int n0 = blockIdx.x * 128;

    // staging coords: thread t -> row = t>>1 (0..127), col base = (t&1)*16
    const int row = tid >> 1;
    const int cb  = (tid & 1) * 16;
    const bool avalid = (m0 + row) < NN;

    float4 aR[4], bR[4];

    auto load_regs = [&](int it) {
        const float* asrc = A  + (size_t)(m0 + row) * K + it * 32 + cb;
        const float* bsrc = BT + (size_t)(n0 + row) * K + it * 32 + cb;
#pragma unroll
        for (int i = 0; i < 4; i++) {
            aR[i] = avalid ? *(const float4*)(asrc + i * 4)
                           : make_float4(0.f, 0.f, 0.f, 0.f);
            bR[i] = *(const float4*)(bsrc + i * 4);
        }
    };

    auto store_smem = [&](int buf, int it) {
        float* As = sm + buf * BUF_FLOATS;
        float* Bs = As + 128 * GLD;
        float* ad = As + row * GLD + cb;
        float* bd = Bs + row * GLD + cb;
#pragma unroll
        for (int i = 0; i < 4; i++) {
            float4 v = aR[i];
            if (G == 1) {
                const float4 bp = *(const float4*)(bias + it * 32 + cb + i * 4);
                v.x = fmaxf(v.x + bp.x, 0.f);
                v.y = fmaxf(v.y + bp.y, 0.f);
                v.z = fmaxf(v.z + bp.z, 0.f);
                v.w = fmaxf(v.w + bp.w, 0.f);
            }
            float4 o;
            o.x = __uint_as_float(f2tf32(v.x));
            o.y = __uint_as_float(f2tf32(v.y));
            o.z = __uint_as_float(f2tf32(v.z));
            o.w = __uint_as_float(f2tf32(v.w));
            *(float4*)(ad + i * 4) = o;
            *(float4*)(bd + i * 4) = bR[i];
        }
    };

    wmma::fragment<wmma::accumulator, 16, 16, 8, float> acc[4][2];
#pragma unroll
    for (int t = 0; t < 4; t++)
#pragma unroll
        for (int u = 0; u < 2; u++) wmma::fill_fragment(acc[t][u], 0.0f);

    load_regs(0);
    store_smem(0, 0);
    __syncthreads();

    for (int it = 0; it < NIT; it++) {
        int buf = it & 1;
        if (it + 1 < NIT) load_regs(it + 1);

        const float* As = sm + buf * BUF_FLOATS;
        const float* Bs = As + 128 * GLD;
#pragma unroll
        for (int ks = 0; ks < 4; ks++) {
            wmma::fragment<wmma::matrix_a, 16, 16, 8, wmma::precision::tf32, wmma::row_major> af[4];
            wmma::fragment<wmma::matrix_b, 16, 16, 8, wmma::precision::tf32, wmma::col_major> bf[2];
#pragma unroll
            for (int t = 0; t < 4; t++)
                wmma::load_matrix_sync(af[t], As + (warpM * 64 + t * 16) * GLD + ks * 8, GLD);
#pragma unroll
            for (int u = 0; u < 2; u++)
                wmma::load_matrix_sync(bf[u], Bs + (warpN * 32 + u * 16) * GLD + ks * 8, GLD);
#pragma unroll
            for (int t = 0; t < 4; t++)
#pragma unroll
                for (int u = 0; u < 2; u++)
                    wmma::mma_sync(acc[t][u], af[t], bf[u], acc[t][u]);
        }

        if (it + 1 < NIT) {
            store_smem(1 - buf, it + 1);   // disjoint buffer; prior readers done (last barrier)
            __syncthreads();
        }
    }

    // epilogue: raw store (buffers padded to NNP rows)
#pragma unroll
    for (int t = 0; t < 4; t++)
#pragma unroll
        for (int u = 0; u < 2; u++) {
            int m = m0 + warpM * 64 + t * 16;
            int n = n0 + warpN * 32 + u * 16;
            wmma::store_matrix_sync(C + (size_t)m * NC + n, acc[t][u], NC, wmma::mem_row_major);
        }
}

// ---------------- batchnorm ----------------
__global__ void k_colstats() {
    int d = threadIdx.x;
    float s = 0.f, q = 0.f;
    for (int r = blockIdx.x; r < NN; r += gridDim.x) {
        float v = g_agg[(size_t)r * DD + d];
        s += v; q += v * v;
    }
    g_partial[blockIdx.x * DD + d] = s;
    g_partial[(STATS_BLOCKS + blockIdx.x) * DD + d] = q;
}

__global__ void k_colreduce() {
    int d = threadIdx.x;
    float s = 0.f, q = 0.f;
    for (int b = 0; b < STATS_BLOCKS; b++) {
        s += g_partial[b * DD + d];
        q += g_partial[(STATS_BLOCKS + b) * DD + d];
    }
    float mu = s / (float)NN;
    float var = q / (float)NN - mu * mu;
    g_stats[d] = mu;
    g_stats[DD + d] = rsqrtf(var + BN_EPS);
}

__global__ void k_bnrelu(const float* __restrict__ g, const float* __restrict__ b) {
    int idx = blockIdx.x * blockDim.x + threadIdx.x;
    if (idx >= NN * DD) return;
    int d = idx & (DD - 1);
    float z = g_agg[idx];
    float v = (z - g_stats[d]) * g_stats[DD + d] * g[d] + b[d];
    g_h[idx] = fmaxf(v, 0.f);
}

// ---------------- pooling ----------------
__device__ __forceinline__ int lower_bound_dev(const int* a, int n, int key) {
    int lo = 0, hi = n;
    while (lo < hi) {
        int mid = (lo + hi) >> 1;
        if (a[mid] < key) lo = mid + 1; else hi = mid;
    }
    return lo;
}

__global__ void k_pool(const int* __restrict__ batch) {
    int b = blockIdx.x;
    int d = threadIdx.x;
    __shared__ int lo_s, hi_s;
    if (d == 0) {
        lo_s = lower_bound_dev(batch, NN, b);
        hi_s = lower_bound_dev(batch, NN, b + 1);
    }
    __syncthreads();
    int lo = lo_s, hi = hi_s;
    float s = 0.f;
    for (int i = lo; i < hi; i++) s += g_h[(size_t)i * DD + d];
    float c = (float)(hi - lo);
    g_pooled[b * DD + d] = s / fmaxf(c, 1.f);
}

// ---------------- output MLP ----------------
__global__ void k_out(const float* __restrict__ Wo1, const float* __restrict__ bo1,
                      const float* __restrict__ Wo2, const float* __restrict__ bo2,
                      float* __restrict__ out) {
    int b = blockIdx.x;
    int j = threadIdx.x;
    __shared__ float p[DD];
    __shared__ float r0[128], r1[128];
    p[j] = g_pooled[b * DD + j];
    p[j + 128] = g_pooled[b * DD + 128 + j];
    __syncthreads();
    float acc = bo1[j];
    for (int k = 0; k < DD; k++) acc += p[k] * Wo1[k * 128 + j];
    float hv = (acc > 20.f) ? acc : log1pf(expf(acc));
    r0[j] = hv * Wo2[j * 2 + 0];
    r1[j] = hv * Wo2[j * 2 + 1];
    __syncthreads();
    for (int s = 64; s > 0; s >>= 1) {
        if (j < s) { r0[j] += r0[j + s]; r1[j] += r1[j + s]; }
        __syncthreads();
    }
    if (j == 0) {
        out[b * 2 + 0] = r0[0] + bo2[0];
        out[b * 2 + 1] = r1[0] + bo2[1];
    }
}

// ---------------- launch ----------------
extern "C" void kernel_launch(void* const* d_in, const int* in_sizes, int n_in,
                              void* d_out, int out_size) {
    const int*   x          = (const int*)d_in[0];
    const int*   edge_index = (const int*)d_in[1];
    const int*   edge_attr  = (const int*)d_in[2];
    const int*   batch      = (const int*)d_in[3];
    const float* x_emb1     = (const float*)d_in[4];
    const float* x_emb2     = (const float*)d_in[5];
    const float* edge_emb1  = (const float*)d_in[6];
    const float* edge_emb2  = (const float*)d_in[7];
    const float* W1         = (const float*)d_in[8];
    const float* b1         = (const float*)d_in[9];
    const float* W2         = (const float*)d_in[10];
    const float* b2         = (const float*)d_in[11];  // dropped (BN-invariant)
    const float* bn_g       = (const float*)d_in[12];
    const float* bn_b       = (const float*)d_in[13];
    const float* Wo1        = (const float*)d_in[14];
    const float* bo1        = (const float*)d_in[15];
    const float* Wo2        = (const float*)d_in[16];
    const float* bo2        = (const float*)d_in[17];
    float* out = (float*)d_out;
    (void)b2;

    cudaFuncSetAttribute(gemm_wmma<0>, cudaFuncAttributeMaxDynamicSharedMemorySize, GEMM_SMEM);
    cudaFuncSetAttribute(gemm_wmma<1>, cudaFuncAttributeMaxDynamicSharedMemorySize, GEMM_SMEM);

    // CSR build
    k_zero_deg<<<(NN + 255) / 256, 256>>>();
    k_hist<<<(EE + 255) / 256, 256>>>(edge_index);
    k_scan<<<1, 1024>>>();
    k_cursor<<<(NN + 255) / 256, 256>>>();
    k_scatter<<<(EE + 255) / 256, 256>>>(edge_index);
    k_sortseg<<<(NN + 255) / 256, 256>>>();

    // weight transpose + tf32 pre-round
    k_prep_w1t<<<(LL * HID * DD + 255) / 256, 256>>>(W1);
    k_prep_w2t<<<(LL * DD * HID + 255) / 256, 256>>>(W2);

    k_init_h<<<NN, DD>>>(x, x_emb1, x_emb2);

    const int MT = NNP / 128;  // 782
    for (int l = 0; l < LL; l++) {
        k_agg<<<NN, DD>>>(edge_emb1 + (size_t)l * 5 * DD,
                          edge_emb2 + (size_t)l * 3 * DD,
                          edge_index, edge_attr);
        {   // GEMM1: t1 = agg @ W1 (raw)
            dim3 grid(HID / 128, MT);
            gemm_wmma<0><<<grid, 256, GEMM_SMEM>>>(b1 + (size_t)l * HID, l);
        }
        {   // GEMM2: agg = relu(t1 + b1) @ W2 (raw; b2 dropped)
            dim3 grid(DD / 128, MT);
            gemm_wmma<1><<<grid, 256, GEMM_SMEM>>>(b1 + (size_t)l * HID, l);
        }
        k_colstats<<<STATS_BLOCKS, DD>>>();
        k_colreduce<<<1, DD>>>();
        k_bnrelu<<<(NN * DD + 255) / 256, 256>>>(bn_g + l * DD, bn_b + l * DD);
    }

    k_pool<<<BB, DD>>>(batch);
    k_out<<<BB, 128>>>(Wo1, bo1, Wo2, bo2, out);
}

// round 7
// speedup vs baseline: 1.3238x; 1.0024x over previous
#include <cuda_runtime.h>
#include <cuda_bf16.h>
#include <mma.h>
#include <math.h>
#include <stdint.h>

using namespace nvcuda;

// Problem constants
#define NN 100000
#define NNP 100096          // padded to multiple of 128 for unguarded tile stores
#define EE 200000
#define BB 2048
#define DD 256
#define LL 5
#define HID 512
#define BN_EPS 1e-5f
#define STATS_BLOCKS 512

// ---------------- scratch (device globals; no allocation allowed) ------------
__device__ float g_h[NNP * DD];
__device__ float g_agg[NNP * DD];
__device__ float g_t1[(size_t)NNP * HID];
__device__ float g_w1t[(size_t)LL * HID * DD];   // [l][n][k] = W1[l][k][n], tf32-rounded
__device__ float g_w2t[(size_t)LL * DD * HID];   // [l][n][k] = W2[l][k][n], tf32-rounded
__device__ int   g_deg[NN];
__device__ int   g_rowptr[NN + 1];
__device__ int   g_cursor[NN];
__device__ int   g_eid[EE];
__device__ float g_partial[2 * STATS_BLOCKS * DD];
__device__ float g_stats[2 * DD];
__device__ float g_pooled[BB * DD];

static __device__ __forceinline__ uint32_t f2tf32(float x) {
    uint32_t r; asm("cvt.rna.tf32.f32 %0, %1;" : "=r"(r) : "f"(x)); return r;
}
static __device__ __forceinline__ uint32_t smem_u32(const void* p) {
    uint32_t a;
    asm("{ .reg .u64 t; cvta.to.shared.u64 t, %1; cvt.u32.u64 %0, t; }" : "=r"(a) : "l"(p));
    return a;
}
static __device__ __forceinline__ void cp16(uint32_t dst, const void* src) {
    asm volatile("cp.async.cg.shared.global [%0], [%1], 16;" :: "r"(dst), "l"(src));
}
#define CP_COMMIT() asm volatile("cp.async.commit_group;" ::: "memory")
#define CP_WAIT(n)  asm volatile("cp.async.wait_group %0;" :: "n"(n) : "memory")

// ---------------- CSR build ----------------
__global__ void k_zero_deg() {
    int i = blockIdx.x * blockDim.x + threadIdx.x;
    if (i < NN) g_deg[i] = 0;
}

__global__ void k_hist(const int* __restrict__ edge_index) {
    int e = blockIdx.x * blockDim.x + threadIdx.x;
    if (e < EE) atomicAdd(&g_deg[edge_index[EE + e]], 1);
}

__global__ void k_scan() {
    __shared__ int s[1024];
    __shared__ int carry;
    int tid = threadIdx.x;
    if (tid == 0) { carry = 0; g_rowptr[0] = 0; }
    __syncthreads();
    for (int base = 0; base < NN; base += 1024) {
        int i = base + tid;
        int v = (i < NN) ? g_deg[i] : 0;
        s[tid] = v;
        __syncthreads();
        for (int off = 1; off < 1024; off <<= 1) {
            int t = (tid >= off) ? s[tid - off] : 0;
            __syncthreads();
            s[tid] += t;
            __syncthreads();
        }
        if (i < NN) g_rowptr[i + 1] = carry + s[tid];
        __syncthreads();
        if (tid == 0) carry += s[1023];
        __syncthreads();
    }
}

__global__ void k_cursor() {
    int i = blockIdx.x * blockDim.x + threadIdx.x;
    if (i < NN) g_cursor[i] = g_rowptr[i];
}

__global__ void k_scatter(const int* __restrict__ edge_index) {
    int e = blockIdx.x * blockDim.x + threadIdx.x;
    if (e < EE) {
        int pos = atomicAdd(&g_cursor[edge_index[EE + e]], 1);
        g_eid[pos] = e;
    }
}

__global__ void k_sortseg() {
    int i = blockIdx.x * blockDim.x + threadIdx.x;
    if (i >= NN) return;
    int s = g_rowptr[i], e = g_rowptr[i + 1];
    for (int a = s + 1; a < e; a++) {
        int v = g_eid[a];
        int b = a - 1;
        while (b >= s && g_eid[b] > v) { g_eid[b + 1] = g_eid[b]; b--; }
        g_eid[b + 1] = v;
    }
}

// ---------------- weight transpose + tf32 pre-round ----------------
__global__ void k_prep_w1t(const float* __restrict__ W1) {
    int idx = blockIdx.x * blockDim.x + threadIdx.x;
    if (idx >= LL * HID * DD) return;
    int l = idx / (HID * DD);
    int rem = idx - l * (HID * DD);
    int n = rem / DD;
    int k = rem - n * DD;
    g_w1t[idx] = __uint_as_float(f2tf32(W1[(size_t)l * DD * HID + (size_t)k * HID + n]));
}

__global__ void k_prep_w2t(const float* __restrict__ W2) {
    int idx = blockIdx.x * blockDim.x + threadIdx.x;
    if (idx >= LL * DD * HID) return;
    int l = idx / (DD * HID);
    int rem = idx - l * (DD * HID);
    int n = rem / HID;
    int k = rem - n * HID;
    g_w2t[idx] = __uint_as_float(f2tf32(W2[(size_t)l * HID * DD + (size_t)k * DD + n]));
}

// ---------------- h init ----------------
__global__ void k_init_h(const int* __restrict__ x,
                         const float* __restrict__ emb1,
                         const float* __restrict__ emb2) {
    int i = blockIdx.x;
    int d = threadIdx.x;
    int a = x[i * 2 + 0], c = x[i * 2 + 1];
    g_h[i * DD + d] = emb1[a * DD + d] + emb2[c * DD + d];
}

// ---------------- aggregation (stores tf32-rounded: only GEMM1 consumes) ----
__global__ void k_agg(const float* __restrict__ e1,
                      const float* __restrict__ e2,
                      const int* __restrict__ edge_index,
                      const int* __restrict__ edge_attr) {
    int i = blockIdx.x;
    int d = threadIdx.x;
    __shared__ float s1[5 * DD];
    __shared__ float s2[3 * DD];
    for (int t = d; t < 5 * DD; t += DD) s1[t] = e1[t];
    for (int t = d; t < 3 * DD; t += DD) s2[t] = e2[t];
    __syncthreads();
    float acc = g_h[i * DD + d] + s1[4 * DD + d] + s2[d];
    int s = g_rowptr[i], e = g_rowptr[i + 1];
    for (int p = s; p < e; p++) {
        int eid = g_eid[p];
        int sn = edge_index[eid];
        int bt = edge_attr[eid * 2 + 0];
        int bd = edge_attr[eid * 2 + 1];
        acc += g_h[sn * DD + d] + s1[bt * DD + d] + s2[bd * DD + d];
    }
    g_agg[i * DD + d] = __uint_as_float(f2tf32(acc));
}

// =================== wmma tf32 GEMM, cp.async double-buffered ===============
// G==0: g_t1 = tf32round(relu(g_agg @ W1 + b1))   (bias/relu/round in epilogue)
// G==1: g_agg = g_t1 @ W2                          (raw; b2 dropped — BN-invariant)
// BM=128, BN=128, BK=32. 8 warps = 2(M) x 4(N); warp tile 64x32 = 4x2 wmma tiles.
// 2 CTAs/SM (73.7KB smem each). Staging is pure cp.async (inputs pre-rounded).
#define GLD 36                            // SMEM leading dim (32 + pad 4); row = 144B
#define STG_FLOATS (2 * 128 * GLD)        // A + B per stage = 9216 floats
#define GEMM_SMEM (2 * STG_FLOATS * 4)    // 73728 bytes
#define ELD 132                           // epilogue tile leading dim

template<int G>
__global__ __launch_bounds__(256, 2)
void gemm_wmma(const float* __restrict__ bias, int l) {
    constexpr int K  = (G == 0) ? DD : HID;
    constexpr int NC = (G == 0) ? HID : DD;
    constexpr int NIT = K / 32;

    const float* __restrict__ A = (G == 0) ? (const float*)g_agg : (const float*)g_t1;
    float* __restrict__ C = (G == 0) ? (float*)g_t1 : (float*)g_agg;
    const float* __restrict__ BT =
        ((G == 0) ? (const float*)g_w1t : (const float*)g_w2t) + (size_t)l * K * NC;

    extern __shared__ float sm[];

    const int tid = threadIdx.x;
    const int wid = tid >> 5;
    const int warpM = wid & 1;    // 0..1  (64 rows each)
    const int warpN = wid >> 1;   // 0..3  (32 cols each)
    const int m0 = blockIdx.y * 128;
    const int n0 = blockIdx.x * 128;

    // staging coords: thread t -> row = t>>1 (0..127), col base = (t&1)*16
    const int row = tid >> 1;
    const int cb  = (tid & 1) * 16;

    const uint32_t smA[2] = { smem_u32(sm) + (uint32_t)(row * GLD + cb) * 4u,
                              smem_u32(sm) + (uint32_t)(STG_FLOATS + row * GLD + cb) * 4u };
    const uint32_t smB[2] = { smA[0] + 128u * GLD * 4u, smA[1] + 128u * GLD * 4u };
    const float* gA = A  + (size_t)(m0 + row) * K + cb;   // rows < NNP always valid
    const float* gB = BT + (size_t)(n0 + row) * K + cb;

    auto issue_stage = [&](int it, int buf) {
        const float* a = gA + it * 32;
        const float* b = gB + it * 32;
#pragma unroll
        for (int i = 0; i < 4; i++) {
            cp16(smA[buf] + i * 16u, a + i * 4);
            cp16(smB[buf] + i * 16u, b + i * 4);
        }
        CP_COMMIT();
    };

    wmma::fragment<wmma::accumulator, 16, 16, 8, float> acc[4][2];
#pragma unroll
    for (int t = 0; t < 4; t++)
#pragma unroll
        for (int u = 0; u < 2; u++) wmma::fill_fragment(acc[t][u], 0.0f);

    issue_stage(0, 0);
    if (NIT > 1) issue_stage(1, 1);

    for (int it = 0; it < NIT; it++) {
        int buf = it & 1;
        if (it == NIT - 1) CP_WAIT(0); else CP_WAIT(1);
        __syncthreads();

        const float* As = sm + buf * STG_FLOATS;
        const float* Bs = As + 128 * GLD;
#pragma unroll
        for (int ks = 0; ks < 4; ks++) {
            wmma::fragment<wmma::matrix_a, 16, 16, 8, wmma::precision::tf32, wmma::row_major> af[4];
            wmma::fragment<wmma::matrix_b, 16, 16, 8, wmma::precision::tf32, wmma::col_major> bf[2];
#pragma unroll
            for (int t = 0; t < 4; t++)
                wmma::load_matrix_sync(af[t], As + (warpM * 64 + t * 16) * GLD + ks * 8, GLD);
#pragma unroll
            for (int u = 0; u < 2; u++)
                wmma::load_matrix_sync(bf[u], Bs + (warpN * 32 + u * 16) * GLD + ks * 8, GLD);
#pragma unroll
            for (int t = 0; t < 4; t++)
#pragma unroll
                for (int u = 0; u < 2; u++)
                    wmma::mma_sync(acc[t][u], af[t], bf[u], acc[t][u]);
        }

        if (it + 2 < NIT) {
            __syncthreads();              // all warps done reading buf before refill
            issue_stage(it + 2, buf);
        }
    }

    if (G == 0) {
        // epilogue via SMEM: fuse b1 + ReLU + tf32-round, then store t1
        __syncthreads();
        float* ep = sm;   // 128 x ELD = 67584 B <= GEMM_SMEM
#pragma unroll
        for (int t = 0; t < 4; t++)
#pragma unroll
            for (int u = 0; u < 2; u++)
                wmma::store_matrix_sync(ep + (warpM * 64 + t * 16) * ELD + warpN * 32 + u * 16,
                                        acc[t][u], ELD, wmma::mem_row_major);
        __syncthreads();
        const int c0 = (tid & 1) * 64;
        float* crow = C + (size_t)(m0 + row) * NC + n0 + c0;
        const float* brow = bias + n0 + c0;
        const float* srow = ep + row * ELD + c0;
#pragma unroll
        for (int i = 0; i < 16; i++) {
            float4 v = *(const float4*)(srow + i * 4);
            float4 bp = *(const float4*)(brow + i * 4);
            float4 o;
            o.x = __uint_as_float(f2tf32(fmaxf(v.x + bp.x, 0.f)));
            o.y = __uint_as_float(f2tf32(fmaxf(v.y + bp.y, 0.f)));
            o.z = __uint_as_float(f2tf32(fmaxf(v.z + bp.z, 0.f)));
            o.w = __uint_as_float(f2tf32(fmaxf(v.w + bp.w, 0.f)));
            *(float4*)(crow + i * 4) = o;
        }
    } else {
        // raw store (buffers padded to NNP rows)
#pragma unroll
        for (int t = 0; t < 4; t++)
#pragma unroll
            for (int u = 0; u < 2; u++) {
                int m = m0 + warpM * 64 + t * 16;
                int n = n0 + warpN * 32 + u * 16;
                wmma::store_matrix_sync(C + (size_t)m * NC + n, acc[t][u], NC, wmma::mem_row_major);
            }
    }
}

// ---------------- batchnorm ----------------
__global__ void k_colstats() {
    int d = threadIdx.x;
    float s = 0.f, q = 0.f;
    for (int r = blockIdx.x; r < NN; r += gridDim.x) {
        float v = g_agg[(size_t)r * DD + d];
        s += v; q += v * v;
    }
    g_partial[blockIdx.x * DD + d] = s;
    g_partial[(STATS_BLOCKS + blockIdx.x) * DD + d] = q;
}

__global__ void k_colreduce() {
    int d = threadIdx.x;
    float s = 0.f, q = 0.f;
    for (int b = 0; b < STATS_BLOCKS; b++) {
        s += g_partial[b * DD + d];
        q += g_partial[(STATS_BLOCKS + b) * DD + d];
    }
    float mu = s / (float)NN;
    float var = q / (float)NN - mu * mu;
    g_stats[d] = mu;
    g_stats[DD + d] = rsqrtf(var + BN_EPS);
}

__global__ void k_bnrelu(const float* __restrict__ g, const float* __restrict__ b) {
    int idx = blockIdx.x * blockDim.x + threadIdx.x;
    if (idx >= NN * DD) return;
    int d = idx & (DD - 1);
    float z = g_agg[idx];
    float v = (z - g_stats[d]) * g_stats[DD + d] * g[d] + b[d];
    g_h[idx] = fmaxf(v, 0.f);
}

// ---------------- pooling ----------------
__device__ __forceinline__ int lower_bound_dev(const int* a, int n, int key) {
    int lo = 0, hi = n;
    while (lo < hi) {
        int mid = (lo + hi) >> 1;
        if (a[mid] < key) lo = mid + 1; else hi = mid;
    }
    return lo;
}

__global__ void k_pool(const int* __restrict__ batch) {
    int b = blockIdx.x;
    int d = threadIdx.x;
    __shared__ int lo_s, hi_s;
    if (d == 0) {
        lo_s = lower_bound_dev(batch, NN, b);
        hi_s = lower_bound_dev(batch, NN, b + 1);
    }
    __syncthreads();
    int lo = lo_s, hi = hi_s;
    float s = 0.f;
    for (int i = lo; i < hi; i++) s += g_h[(size_t)i * DD + d];
    float c = (float)(hi - lo);
    g_pooled[b * DD + d] = s / fmaxf(c, 1.f);
}

// ---------------- output MLP ----------------
__global__ void k_out(const float* __restrict__ Wo1, const float* __restrict__ bo1,
                      const float* __restrict__ Wo2, const float* __restrict__ bo2,
                      float* __restrict__ out) {
    int b = blockIdx.x;
    int j = threadIdx.x;
    __shared__ float p[DD];
    __shared__ float r0[128], r1[128];
    p[j] = g_pooled[b * DD + j];
    p[j + 128] = g_pooled[b * DD + 128 + j];
    __syncthreads();
    float acc = bo1[j];
    for (int k = 0; k < DD; k++) acc += p[k] * Wo1[k * 128 + j];
    float hv = (acc > 20.f) ? acc : log1pf(expf(acc));
    r0[j] = hv * Wo2[j * 2 + 0];
    r1[j] = hv * Wo2[j * 2 + 1];
    __syncthreads();
    for (int s = 64; s > 0; s >>= 1) {
        if (j < s) { r0[j] += r0[j + s]; r1[j] += r1[j + s]; }
        __syncthreads();
    }
    if (j == 0) {
        out[b * 2 + 0] = r0[0] + bo2[0];
        out[b * 2 + 1] = r1[0] + bo2[1];
    }
}

// ---------------- launch ----------------
extern "C" void kernel_launch(void* const* d_in, const int* in_sizes, int n_in,
                              void* d_out, int out_size) {
    const int*   x          = (const int*)d_in[0];
    const int*   edge_index = (const int*)d_in[1];
    const int*   edge_attr  = (const int*)d_in[2];
    const int*   batch      = (const int*)d_in[3];
    const float* x_emb1     = (const float*)d_in[4];
    const float* x_emb2     = (const float*)d_in[5];
    const float* edge_emb1  = (const float*)d_in[6];
    const float* edge_emb2  = (const float*)d_in[7];
    const float* W1         = (const float*)d_in[8];
    const float* b1         = (const float*)d_in[9];
    const float* W2         = (const float*)d_in[10];
    const float* b2         = (const float*)d_in[11];  // dropped (BN-invariant)
    const float* bn_g       = (const float*)d_in[12];
    const float* bn_b       = (const float*)d_in[13];
    const float* Wo1        = (const float*)d_in[14];
    const float* bo1        = (const float*)d_in[15];
    const float* Wo2        = (const float*)d_in[16];
    const float* bo2        = (const float*)d_in[17];
    float* out = (float*)d_out;
    (void)b2;

    cudaFuncSetAttribute(gemm_wmma<0>, cudaFuncAttributeMaxDynamicSharedMemorySize, GEMM_SMEM);
    cudaFuncSetAttribute(gemm_wmma<1>, cudaFuncAttributeMaxDynamicSharedMemorySize, GEMM_SMEM);

    // CSR build
    k_zero_deg<<<(NN + 255) / 256, 256>>>();
    k_hist<<<(EE + 255) / 256, 256>>>(edge_index);
    k_scan<<<1, 1024>>>();
    k_cursor<<<(NN + 255) / 256, 256>>>();
    k_scatter<<<(EE + 255) / 256, 256>>>(edge_index);
    k_sortseg<<<(NN + 255) / 256, 256>>>();

    // weight transpose + tf32 pre-round
    k_prep_w1t<<<(LL * HID * DD + 255) / 256, 256>>>(W1);
    k_prep_w2t<<<(LL * DD * HID + 255) / 256, 256>>>(W2);

    k_init_h<<<NN, DD>>>(x, x_emb1, x_emb2);

    const int MT = NNP / 128;  // 782
    for (int l = 0; l < LL; l++) {
        k_agg<<<NN, DD>>>(edge_emb1 + (size_t)l * 5 * DD,
                          edge_emb2 + (size_t)l * 3 * DD,
                          edge_index, edge_attr);
        {   // GEMM1: t1 = tf32round(relu(agg @ W1 + b1))
            dim3 grid(HID / 128, MT);
            gemm_wmma<0><<<grid, 256, GEMM_SMEM>>>(b1 + (size_t)l * HID, l);
        }
        {   // GEMM2: agg = t1 @ W2 (raw; b2 dropped)
            dim3 grid(DD / 128, MT);
            gemm_wmma<1><<<grid, 256, GEMM_SMEM>>>(b1 + (size_t)l * HID, l);
        }
        k_colstats<<<STATS_BLOCKS, DD>>>();
        k_colreduce<<<1, DD>>>();
        k_bnrelu<<<(NN * DD + 255) / 256, 256>>>(bn_g + l * DD, bn_b + l * DD);
    }

    k_pool<<<BB, DD>>>(batch);
    k_out<<<BB, 128>>>(Wo1, bo1, Wo2, bo2, out);
}

// round 8
// speedup vs baseline: 2.6348x; 1.9904x over previous
#include <cuda_runtime.h>
#include <cuda_fp16.h>
#include <mma.h>
#include <math.h>
#include <stdint.h>

using namespace nvcuda;

// Problem constants
#define NN 100000
#define NNP 100096          // padded to multiple of 128 for unguarded tile stores
#define EE 200000
#define BB 2048
#define DD 256
#define LL 5
#define HID 512
#define BN_EPS 1e-5f
#define STATS_BLOCKS 512
#define AGG_NPB 8

// ---------------- scratch (device globals; no allocation allowed) ------------
__device__ float  g_h[NNP * DD];
__device__ float  g_agg[NNP * DD];                 // z (GEMM2 output, fp32 for BN)
__device__ __half g_aggh[(size_t)NNP * DD];        // GEMM1 input (half)
__device__ __half g_t1h[(size_t)NNP * HID];        // GEMM2 input (half)
__device__ __half g_w1h[(size_t)LL * HID * DD];    // [l][n][k] = W1[l][k][n]
__device__ __half g_w2h[(size_t)LL * DD * HID];    // [l][n][k] = W2[l][k][n]
__device__ int    g_deg[NN];
__device__ int    g_rowptr[NN + 1];
__device__ int    g_cursor[NN];
__device__ int    g_eid[EE];
__device__ float  g_partial[2 * STATS_BLOCKS * DD];
__device__ float  g_stats[2 * DD];
__device__ float  g_pooled[BB * DD];

static __device__ __forceinline__ uint32_t smem_u32(const void* p) {
    uint32_t a;
    asm("{ .reg .u64 t; cvta.to.shared.u64 t, %1; cvt.u32.u64 %0, t; }" : "=r"(a) : "l"(p));
    return a;
}
static __device__ __forceinline__ void cp16(uint32_t dst, const void* src) {
    asm volatile("cp.async.cg.shared.global [%0], [%1], 16;" :: "r"(dst), "l"(src));
}
#define CP_COMMIT() asm volatile("cp.async.commit_group;" ::: "memory")
#define CP_WAIT(n)  asm volatile("cp.async.wait_group %0;" :: "n"(n) : "memory")

// ---------------- CSR build ----------------
__global__ void k_zero_deg() {
    int i = blockIdx.x * blockDim.x + threadIdx.x;
    if (i < NN) g_deg[i] = 0;
}

__global__ void k_hist(const int* __restrict__ edge_index) {
    int e = blockIdx.x * blockDim.x + threadIdx.x;
    if (e < EE) atomicAdd(&g_deg[edge_index[EE + e]], 1);
}

__global__ void k_scan() {
    __shared__ int s[1024];
    __shared__ int carry;
    int tid = threadIdx.x;
    if (tid == 0) { carry = 0; g_rowptr[0] = 0; }
    __syncthreads();
    for (int base = 0; base < NN; base += 1024) {
        int i = base + tid;
        int v = (i < NN) ? g_deg[i] : 0;
        s[tid] = v;
        __syncthreads();
        for (int off = 1; off < 1024; off <<= 1) {
            int t = (tid >= off) ? s[tid - off] : 0;
            __syncthreads();
            s[tid] += t;
            __syncthreads();
        }
        if (i < NN) g_rowptr[i + 1] = carry + s[tid];
        __syncthreads();
        if (tid == 0) carry += s[1023];
        __syncthreads();
    }
}

__global__ void k_cursor() {
    int i = blockIdx.x * blockDim.x + threadIdx.x;
    if (i < NN) g_cursor[i] = g_rowptr[i];
}

__global__ void k_scatter(const int* __restrict__ edge_index) {
    int e = blockIdx.x * blockDim.x + threadIdx.x;
    if (e < EE) {
        int pos = atomicAdd(&g_cursor[edge_index[EE + e]], 1);
        g_eid[pos] = e;
    }
}

__global__ void k_sortseg() {
    int i = blockIdx.x * blockDim.x + threadIdx.x;
    if (i >= NN) return;
    int s = g_rowptr[i], e = g_rowptr[i + 1];
    for (int a = s + 1; a < e; a++) {
        int v = g_eid[a];
        int b = a - 1;
        while (b >= s && g_eid[b] > v) { g_eid[b + 1] = g_eid[b]; b--; }
        g_eid[b + 1] = v;
    }
}

// ---------------- weight transpose -> half ----------------
__global__ void k_prep_w1h(const float* __restrict__ W1) {
    int idx = blockIdx.x * blockDim.x + threadIdx.x;
    if (idx >= LL * HID * DD) return;
    int l = idx / (HID * DD);
    int rem = idx - l * (HID * DD);
    int n = rem / DD;
    int k = rem - n * DD;
    g_w1h[idx] = __float2half_rn(W1[(size_t)l * DD * HID + (size_t)k * HID + n]);
}

__global__ void k_prep_w2h(const float* __restrict__ W2) {
    int idx = blockIdx.x * blockDim.x + threadIdx.x;
    if (idx >= LL * DD * HID) return;
    int l = idx / (DD * HID);
    int rem = idx - l * (DD * HID);
    int n = rem / HID;
    int k = rem - n * HID;
    g_w2h[idx] = __float2half_rn(W2[(size_t)l * HID * DD + (size_t)k * DD + n]);
}

// ---------------- h init ----------------
__global__ void k_init_h(const int* __restrict__ x,
                         const float* __restrict__ emb1,
                         const float* __restrict__ emb2) {
    int i = blockIdx.x;
    int d = threadIdx.x;
    int a = x[i * 2 + 0], c = x[i * 2 + 1];
    g_h[i * DD + d] = emb1[a * DD + d] + emb2[c * DD + d];
}

// ---------------- aggregation: 8 nodes/block, writes half for GEMM1 ---------
__global__ void k_agg(const float* __restrict__ e1,
                      const float* __restrict__ e2,
                      const int* __restrict__ edge_index,
                      const int* __restrict__ edge_attr) {
    int base = blockIdx.x * AGG_NPB;
    int d = threadIdx.x;
    __shared__ float s1[5 * DD];
    __shared__ float s2[3 * DD];
    for (int t = d; t < 5 * DD; t += DD) s1[t] = e1[t];
    for (int t = d; t < 3 * DD; t += DD) s2[t] = e2[t];
    __syncthreads();
    const float selfc = s1[4 * DD + d] + s2[d];
#pragma unroll
    for (int j = 0; j < AGG_NPB; j++) {
        int i = base + j;
        if (i >= NN) break;
        float acc = g_h[(size_t)i * DD + d] + selfc;
        int s = g_rowptr[i], e = g_rowptr[i + 1];
        for (int p = s; p < e; p++) {
            int eid = g_eid[p];
            int sn = edge_index[eid];
            int bt = edge_attr[eid * 2 + 0];
            int bd = edge_attr[eid * 2 + 1];
            acc += g_h[(size_t)sn * DD + d] + s1[bt * DD + d] + s2[bd * DD + d];
        }
        g_aggh[(size_t)i * DD + d] = __float2half_rn(acc);
    }
}

// =================== wmma fp16 GEMM (fp32 accum), cp.async ===================
// G==0: g_t1h = half(relu(g_aggh @ W1h + b1))   (bias/relu in epilogue)
// G==1: g_agg = g_t1h @ W2h                      (fp32 out; b2 dropped — BN-invariant)
// BM=128, BN=128, BK=32. 8 warps = 2(M) x 4(N); warp tile 64x32 = 4x2 wmma tiles.
#define HLD 40                             // halfs per SMEM row (32 + pad 8) = 80B
#define STG_HALFS (2 * 128 * HLD)          // A + B per stage = 10240 halfs
#define GEMM_SMEM (2 * STG_HALFS * 2)      // 40960 bytes (double buffered)
#define ELD 68                             // epilogue float tile leading dim

template<int G>
__global__ __launch_bounds__(256, 2)
void gemm_wmma(const float* __restrict__ bias, int l) {
    constexpr int K  = (G == 0) ? DD : HID;
    constexpr int NC = (G == 0) ? HID : DD;
    constexpr int NIT = K / 32;

    const __half* __restrict__ A = (G == 0) ? (const __half*)g_aggh : (const __half*)g_t1h;
    const __half* __restrict__ BT =
        ((G == 0) ? (const __half*)g_w1h : (const __half*)g_w2h) + (size_t)l * K * NC;

    extern __shared__ __half smh[];

    const int tid = threadIdx.x;
    const int wid = tid >> 5;
    const int warpM = wid & 1;    // 0..1  (64 rows)
    const int warpN = wid >> 1;   // 0..3  (32 cols)
    const int m0 = blockIdx.y * 128;
    const int n0 = blockIdx.x * 128;

    // staging: thread t -> row = t>>1 (0..127), 32B segment = (t&1)
    const int row = tid >> 1;
    const int seg = tid & 1;

    const uint32_t smBase = smem_u32(smh);
    const uint32_t smA[2] = { smBase + (uint32_t)(row * HLD + seg * 16) * 2u,
                              smBase + (uint32_t)(STG_HALFS + row * HLD + seg * 16) * 2u };
    const uint32_t smB[2] = { smA[0] + 128u * HLD * 2u, smA[1] + 128u * HLD * 2u };
    const __half* gA = A  + (size_t)(m0 + row) * K + seg * 16;
    const __half* gB = BT + (size_t)(n0 + row) * K + seg * 16;

    auto issue_stage = [&](int it, int buf) {
        const __half* a = gA + it * 32;
        const __half* b = gB + it * 32;
        cp16(smA[buf],       a);
        cp16(smA[buf] + 16u, a + 8);
        cp16(smB[buf],       b);
        cp16(smB[buf] + 16u, b + 8);
        CP_COMMIT();
    };

    wmma::fragment<wmma::accumulator, 16, 16, 16, float> acc[4][2];
#pragma unroll
    for (int t = 0; t < 4; t++)
#pragma unroll
        for (int u = 0; u < 2; u++) wmma::fill_fragment(acc[t][u], 0.0f);

    issue_stage(0, 0);
    issue_stage(1, 1);

    for (int it = 0; it < NIT; it++) {
        int buf = it & 1;
        if (it == NIT - 1) CP_WAIT(0); else CP_WAIT(1);
        __syncthreads();

        const __half* As = smh + buf * STG_HALFS;
        const __half* Bs = As + 128 * HLD;
#pragma unroll
        for (int ks = 0; ks < 2; ks++) {
            wmma::fragment<wmma::matrix_a, 16, 16, 16, __half, wmma::row_major> af[4];
            wmma::fragment<wmma::matrix_b, 16, 16, 16, __half, wmma::col_major> bf[2];
#pragma unroll
            for (int t = 0; t < 4; t++)
                wmma::load_matrix_sync(af[t], As + (warpM * 64 + t * 16) * HLD + ks * 16, HLD);
#pragma unroll
            for (int u = 0; u < 2; u++)
                wmma::load_matrix_sync(bf[u], Bs + (warpN * 32 + u * 16) * HLD + ks * 16, HLD);
#pragma unroll
            for (int t = 0; t < 4; t++)
#pragma unroll
                for (int u = 0; u < 2; u++)
                    wmma::mma_sync(acc[t][u], af[t], bf[u], acc[t][u]);
        }

        if (it + 2 < NIT) {
            __syncthreads();              // all warps done reading buf before refill
            issue_stage(it + 2, buf);
        }
    }

    if (G == 0) {
        // epilogue via SMEM (two 128x64 passes): fuse b1 + ReLU, store half t1
        float* ep = (float*)smh;          // 128 x ELD floats = 34816 B <= 40960
        const int coff = seg * 32;
#pragma unroll
        for (int p = 0; p < 2; p++) {
            __syncthreads();
            if ((warpN >> 1) == p) {
#pragma unroll
                for (int t = 0; t < 4; t++)
#pragma unroll
                    for (int u = 0; u < 2; u++)
                        wmma::store_matrix_sync(
                            ep + (warpM * 64 + t * 16) * ELD + (warpN & 1) * 32 + u * 16,
                            acc[t][u], ELD, wmma::mem_row_major);
            }
            __syncthreads();
            const float* srow = ep + row * ELD + coff;
            const float* brow = bias + n0 + p * 64 + coff;
            __half2* crow = (__half2*)(g_t1h + (size_t)(m0 + row) * NC + n0 + p * 64 + coff);
#pragma unroll
            for (int i = 0; i < 16; i++) {
                float2 v = *(const float2*)(srow + 2 * i);
                float2 bp = *(const float2*)(brow + 2 * i);
                crow[i] = __floats2half2_rn(fmaxf(v.x + bp.x, 0.f), fmaxf(v.y + bp.y, 0.f));
            }
        }
    } else {
        // raw fp32 store to g_agg (buffer padded to NNP rows)
#pragma unroll
        for (int t = 0; t < 4; t++)
#pragma unroll
            for (int u = 0; u < 2; u++) {
                int m = m0 + warpM * 64 + t * 16;
                int n = n0 + warpN * 32 + u * 16;
                wmma::store_matrix_sync(g_agg + (size_t)m * NC + n, acc[t][u], NC,
                                        wmma::mem_row_major);
            }
    }
}

// ---------------- batchnorm ----------------
__global__ void k_colstats() {
    int d = threadIdx.x;
    float s = 0.f, q = 0.f;
    for (int r = blockIdx.x; r < NN; r += gridDim.x) {
        float v = g_agg[(size_t)r * DD + d];
        s += v; q += v * v;
    }
    g_partial[blockIdx.x * DD + d] = s;
    g_partial[(STATS_BLOCKS + blockIdx.x) * DD + d] = q;
}

__global__ void k_colreduce() {
    int d = threadIdx.x;
    float s = 0.f, q = 0.f;
    for (int b = 0; b < STATS_BLOCKS; b++) {
        s += g_partial[b * DD + d];
        q += g_partial[(STATS_BLOCKS + b) * DD + d];
    }
    float mu = s / (float)NN;
    float var = q / (float)NN - mu * mu;
    g_stats[d] = mu;
    g_stats[DD + d] = rsqrtf(var + BN_EPS);
}

__global__ void k_bnrelu(const float* __restrict__ g, const float* __restrict__ b) {
    int idx = blockIdx.x * blockDim.x + threadIdx.x;
    if (idx >= NN * DD) return;
    int d = idx & (DD - 1);
    float z = g_agg[idx];
    float v = (z - g_stats[d]) * g_stats[DD + d] * g[d] + b[d];
    g_h[idx] = fmaxf(v, 0.f);
}

// ---------------- pooling ----------------
__device__ __forceinline__ int lower_bound_dev(const int* a, int n, int key) {
    int lo = 0, hi = n;
    while (lo < hi) {
        int mid = (lo + hi) >> 1;
        if (a[mid] < key) lo = mid + 1; else hi = mid;
    }
    return lo;
}

__global__ void k_pool(const int* __restrict__ batch) {
    int b = blockIdx.x;
    int d = threadIdx.x;
    __shared__ int lo_s, hi_s;
    if (d == 0) {
        lo_s = lower_bound_dev(batch, NN, b);
        hi_s = lower_bound_dev(batch, NN, b + 1);
    }
    __syncthreads();
    int lo = lo_s, hi = hi_s;
    float s = 0.f;
    for (int i = lo; i < hi; i++) s += g_h[(size_t)i * DD + d];
    float c = (float)(hi - lo);
    g_pooled[b * DD + d] = s / fmaxf(c, 1.f);
}

// ---------------- output MLP ----------------
__global__ void k_out(const float* __restrict__ Wo1, const float* __restrict__ bo1,
                      const float* __restrict__ Wo2, const float* __restrict__ bo2,
                      float* __restrict__ out) {
    int b = blockIdx.x;
    int j = threadIdx.x;
    __shared__ float p[DD];
    __shared__ float r0[128], r1[128];
    p[j] = g_pooled[b * DD + j];
    p[j + 128] = g_pooled[b * DD + 128 + j];
    __syncthreads();
    float acc = bo1[j];
    for (int k = 0; k < DD; k++) acc += p[k] * Wo1[k * 128 + j];
    float hv = (acc > 20.f) ? acc : log1pf(expf(acc));
    r0[j] = hv * Wo2[j * 2 + 0];
    r1[j] = hv * Wo2[j * 2 + 1];
    __syncthreads();
    for (int s = 64; s > 0; s >>= 1) {
        if (j < s) { r0[j] += r0[j + s]; r1[j] += r1[j + s]; }
        __syncthreads();
    }
    if (j == 0) {
        out[b * 2 + 0] = r0[0] + bo2[0];
        out[b * 2 + 1] = r1[0] + bo2[1];
    }
}

// ---------------- launch ----------------
extern "C" void kernel_launch(void* const* d_in, const int* in_sizes, int n_in,
                              void* d_out, int out_size) {
    const int*   x          = (const int*)d_in[0];
    const int*   edge_index = (const int*)d_in[1];
    const int*   edge_attr  = (const int*)d_in[2];
    const int*   batch      = (const int*)d_in[3];
    const float* x_emb1     = (const float*)d_in[4];
    const float* x_emb2     = (const float*)d_in[5];
    const float* edge_emb1  = (const float*)d_in[6];
    const float* edge_emb2  = (const float*)d_in[7];
    const float* W1         = (const float*)d_in[8];
    const float* b1         = (const float*)d_in[9];
    const float* W2         = (const float*)d_in[10];
    const float* b2         = (const float*)d_in[11];  // dropped (BN-invariant)
    const float* bn_g       = (const float*)d_in[12];
    const float* bn_b       = (const float*)d_in[13];
    const float* Wo1        = (const float*)d_in[14];
    const float* bo1        = (const float*)d_in[15];
    const float* Wo2        = (const float*)d_in[16];
    const float* bo2        = (const float*)d_in[17];
    float* out = (float*)d_out;
    (void)b2;

    cudaFuncSetAttribute(gemm_wmma<0>, cudaFuncAttributeMaxDynamicSharedMemorySize, GEMM_SMEM);
    cudaFuncSetAttribute(gemm_wmma<1>, cudaFuncAttributeMaxDynamicSharedMemorySize, GEMM_SMEM);

    // CSR build
    k_zero_deg<<<(NN + 255) / 256, 256>>>();
    k_hist<<<(EE + 255) / 256, 256>>>(edge_index);
    k_scan<<<1, 1024>>>();
    k_cursor<<<(NN + 255) / 256, 256>>>();
    k_scatter<<<(EE + 255) / 256, 256>>>(edge_index);
    k_sortseg<<<(NN + 255) / 256, 256>>>();

    // weight transpose -> half
    k_prep_w1h<<<(LL * HID * DD + 255) / 256, 256>>>(W1);
    k_prep_w2h<<<(LL * DD * HID + 255) / 256, 256>>>(W2);

    k_init_h<<<NN, DD>>>(x, x_emb1, x_emb2);

    const int MT = NNP / 128;  // 782
    for (int l = 0; l < LL; l++) {
        k_agg<<<(NN + AGG_NPB - 1) / AGG_NPB, DD>>>(edge_emb1 + (size_t)l * 5 * DD,
                                                    edge_emb2 + (size_t)l * 3 * DD,
                                                    edge_index, edge_attr);
        {   // GEMM1: t1h = half(relu(aggh @ W1 + b1))
            dim3 grid(HID / 128, MT);
            gemm_wmma<0><<<grid, 256, GEMM_SMEM>>>(b1 + (size_t)l * HID, l);
        }
        {   // GEMM2: agg = t1h @ W2 (fp32 out; b2 dropped)
            dim3 grid(DD / 128, MT);
            gemm_wmma<1><<<grid, 256, GEMM_SMEM>>>(b1 + (size_t)l * HID, l);
        }
        k_colstats<<<STATS_BLOCKS, DD>>>();
        k_colreduce<<<1, DD>>>();
        k_bnrelu<<<(NN * DD + 255) / 256, 256>>>(bn_g + l * DD, bn_b + l * DD);
    }

    k_pool<<<BB, DD>>>(batch);
    k_out<<<BB, 128>>>(Wo1, bo1, Wo2, bo2, out);
}